// round 3
// baseline (speedup 1.0000x reference)
#include <cuda_runtime.h>
#include <cstdint>

#define Bdim 2
#define Hdim 16
#define Sdim 2048
#define Ddim 128
#define NT 16
#define NTHREADS 256

// smem strides (in floats) chosen for bank-conflict-free fragment loads
#define QSTRIDE 136
#define KSTRIDE 136
#define VSTRIDE 132

#define QS_OFF 0
#define KS_OFF (128 * QSTRIDE)
#define VS_OFF (KS_OFF + 128 * KSTRIDE)
#define SMEM_WORDS (VS_OFF + 128 * VSTRIDE)
#define SMEM_BYTES (SMEM_WORDS * 4)   // 206848

#define SHIFT1 1.00048828125f   // 1 + 2^-11 : Q-side truncation-bias compensation
#define SHIFTH 1.00024411f      // sqrt(1 + 2^-11) : P-side (applied before square)

// ---------------------------------------------------------------------------
static __device__ __forceinline__ uint32_t cvt_tf32(float f) {
    uint32_t r;
    asm("cvt.rna.tf32.f32 %0, %1;" : "=r"(r) : "f"(f));
    return r;
}

static __device__ __forceinline__ void mma8(float* d,
        uint32_t a0, uint32_t a1, uint32_t a2, uint32_t a3,
        uint32_t b0, uint32_t b1) {
    asm volatile(
        "mma.sync.aligned.m16n8k8.row.col.f32.tf32.tf32.f32 "
        "{%0,%1,%2,%3}, {%4,%5,%6,%7}, {%8,%9}, {%0,%1,%2,%3};"
        : "+f"(d[0]), "+f"(d[1]), "+f"(d[2]), "+f"(d[3])
        : "r"(a0), "r"(a1), "r"(a2), "r"(a3), "r"(b0), "r"(b1));
}

static __device__ __forceinline__ void cp16(const float* smem_dst, const float* gsrc) {
    unsigned sa = (unsigned)__cvta_generic_to_shared(smem_dst);
    asm volatile("cp.async.cg.shared.global [%0], [%1], 16;" :: "r"(sa), "l"(gsrc));
}
#define CP_COMMIT() asm volatile("cp.async.commit_group;" ::: "memory")
#define CP_WAIT(n)  asm volatile("cp.async.wait_group %0;" :: "n"(n) : "memory")

static __device__ __forceinline__ void bar_sync(int id, int cnt) {
    asm volatile("bar.sync %0, %1;" :: "r"(id), "r"(cnt) : "memory");
}

// Issue cp.async for one kv-quarter (32 rows of K and V) of tile `tile`.
// Called by the 128 threads of the half that owns quarter qq; tid_h in [0,128).
static __device__ __forceinline__ void issue_quarter(
        float* sm, const float* __restrict__ kb, const float* __restrict__ vb,
        int qq, int tile, int tid_h) {
    const float* kg = kb + (size_t)(tile * 128 + qq * 32) * Ddim;
    const float* vg = vb + (size_t)(tile * 128 + qq * 32) * Ddim;
    #pragma unroll
    for (int i = 0; i < 8; i++) {
        int c = tid_h + 128 * i;          // 0..1023
        int r = c >> 5, col = (c & 31) << 2;
        cp16(sm + KS_OFF + (qq * 32 + r) * KSTRIDE + col, kg + r * Ddim + col);
    }
    #pragma unroll
    for (int i = 0; i < 8; i++) {
        int c = tid_h + 128 * i;
        int r = c >> 5, col = (c & 31) << 2;
        cp16(sm + VS_OFF + (qq * 32 + r) * VSTRIDE + col, vg + r * Ddim + col);
    }
}

// ---------------------------------------------------------------------------
// One CTA = one (b,h) x one 128-row q-tile. 8 warps: wm = wid&3 (m-position,
// 32 rows each), wn = wid>>2 (kv-half). Each warp: S(m32 x kv32 per phase),
// O partial (m32 x d128). kv-halves run decoupled on named barriers with
// quarter-granular cp.async pipelines. O reduced across halves at the end.
// ---------------------------------------------------------------------------
__global__ void __launch_bounds__(NTHREADS, 1)
attn_relu2_kernel(const float* __restrict__ q, const float* __restrict__ k,
                  const float* __restrict__ v, const float* __restrict__ scale_p,
                  float* __restrict__ out) {
    extern __shared__ float sm[];
    float* QS = sm + QS_OFF;
    float* KS = sm + KS_OFF;
    float* VS = sm + VS_OFF;

    const int tid  = threadIdx.x;
    const int lane = tid & 31;
    const int g    = lane >> 2;    // 0..7
    const int t4   = lane & 3;     // 0..3
    const int wid  = tid >> 5;
    const int wm   = wid & 3;      // m-position
    const int wn   = wid >> 2;     // kv-half
    const int tid_h = tid & 127;

    const int bh = blockIdx.x >> 4;
    const int q0 = (blockIdx.x & 15) << 7;

    const float* kbase = k + (size_t)bh * Sdim * Ddim;
    const float* vbase = v + (size_t)bh * Sdim * Ddim;

    // ---- prologue: stream tile-0 quarters, fill Q ----
    issue_quarter(sm, kbase, vbase, wn * 2 + 0, 0, tid_h); CP_COMMIT();
    issue_quarter(sm, kbase, vbase, wn * 2 + 1, 0, tid_h); CP_COMMIT();

    {
        const float scl2 = (*scale_p) * SHIFT1;
        const float* qg = q + ((size_t)bh * Sdim + q0) * Ddim;
        #pragma unroll
        for (int i = 0; i < 16; i++) {
            int c = tid + 256 * i;         // 0..4095
            int r = c >> 5, col = (c & 31) << 2;
            float4 f = *reinterpret_cast<const float4*>(qg + r * Ddim + col);
            uint4 u;
            u.x = cvt_tf32(f.x * scl2); u.y = cvt_tf32(f.y * scl2);
            u.z = cvt_tf32(f.z * scl2); u.w = cvt_tf32(f.w * scl2);
            *reinterpret_cast<uint4*>(QS + r * QSTRIDE + col) = u;
        }
    }
    __syncthreads();

    float O[2][16][4];
    #pragma unroll
    for (int mb = 0; mb < 2; mb++)
        #pragma unroll
        for (int nd = 0; nd < 16; nd++)
            #pragma unroll
            for (int i = 0; i < 4; i++) O[mb][nd][i] = 0.0f;

    // ---- main loop ----
    #pragma unroll 1
    for (int tt = 0; tt < NT; tt++) {
        const bool lastt = (tt == NT - 1);
        #pragma unroll
        for (int p = 0; p < 2; p++) {
            const int qq = wn * 2 + p;     // kv-quarter owned this phase

            if (lastt && p == 1) { CP_WAIT(0); } else { CP_WAIT(1); }
            bar_sync(1 + wn, 128);

            // ---- GEMM1: S = Qs @ K^T over d (16 k-steps, permuted pairs) ----
            float S[2][4][4];
            #pragma unroll
            for (int mb = 0; mb < 2; mb++)
                #pragma unroll
                for (int nb = 0; nb < 4; nb++)
                    #pragma unroll
                    for (int i = 0; i < 4; i++) S[mb][nb][i] = 0.0f;

            #pragma unroll 4
            for (int ks = 0; ks < 16; ks++) {
                uint2 A0[2], A1[2];
                #pragma unroll
                for (int mb = 0; mb < 2; mb++) {
                    int rb = wm * 32 + mb * 16;
                    A0[mb] = *reinterpret_cast<const uint2*>(
                        QS + (rb + g) * QSTRIDE + 8 * ks + 2 * t4);
                    A1[mb] = *reinterpret_cast<const uint2*>(
                        QS + (rb + 8 + g) * QSTRIDE + 8 * ks + 2 * t4);
                }
                #pragma unroll
                for (int nb = 0; nb < 4; nb++) {
                    float2 b = *reinterpret_cast<const float2*>(
                        KS + (qq * 32 + nb * 8 + g) * KSTRIDE + 8 * ks + 2 * t4);
                    uint32_t b0 = __float_as_uint(b.x), b1 = __float_as_uint(b.y);
                    mma8(S[0][nb], A0[0].x, A1[0].x, A0[0].y, A1[0].y, b0, b1);
                    mma8(S[1][nb], A0[1].x, A1[1].x, A0[1].y, A1[1].y, b0, b1);
                }
            }

            // ---- P = tf32(relu(S)^2 * shift); GEMM2: O += P @ V ----
            #pragma unroll
            for (int s2 = 0; s2 < 4; s2++) {
                uint32_t pA[2][4];
                #pragma unroll
                for (int mb = 0; mb < 2; mb++)
                    #pragma unroll
                    for (int i = 0; i < 4; i++) {
                        float f = fmaxf(S[mb][s2][i], 0.0f) * SHIFTH;
                        pA[mb][i] = cvt_tf32(f * f);
                    }
                const float* vrow = VS + (qq * 32 + s2 * 8 + 2 * t4) * VSTRIDE + g;
                #pragma unroll 4
                for (int nd = 0; nd < 16; nd++) {
                    uint32_t b0 = __float_as_uint(vrow[nd * 8]);
                    uint32_t b1 = __float_as_uint(vrow[nd * 8 + VSTRIDE]);
                    // A-frag = (c0, c2, c1, c3) of the S block
                    mma8(O[0][nd], pA[0][0], pA[0][2], pA[0][1], pA[0][3], b0, b1);
                    mma8(O[1][nd], pA[1][0], pA[1][2], pA[1][1], pA[1][3], b0, b1);
                }
            }

            bar_sync(1 + wn, 128);
            if (!lastt) {
                issue_quarter(sm, kbase, vbase, qq, tt + 1, tid_h);
                CP_COMMIT();
            }
        }
    }

    // ---- reduce O across the two kv-halves, write out ----
    __syncthreads();
    float* red = KS;   // reuse 128 x 136 region
    if (wn == 1) {
        #pragma unroll
        for (int mb = 0; mb < 2; mb++) {
            int r0 = wm * 32 + mb * 16 + g;
            #pragma unroll
            for (int nd = 0; nd < 16; nd++) {
                *reinterpret_cast<float2*>(red + r0 * 136 + nd * 8 + 2 * t4) =
                    make_float2(O[mb][nd][0], O[mb][nd][1]);
                *reinterpret_cast<float2*>(red + (r0 + 8) * 136 + nd * 8 + 2 * t4) =
                    make_float2(O[mb][nd][2], O[mb][nd][3]);
            }
        }
    }
    __syncthreads();
    if (wn == 0) {
        float* ob = out + ((size_t)bh * Sdim + q0) * Ddim;
        #pragma unroll
        for (int mb = 0; mb < 2; mb++) {
            int r0 = wm * 32 + mb * 16 + g;
            #pragma unroll
            for (int nd = 0; nd < 16; nd++) {
                float2 ra = *reinterpret_cast<const float2*>(red + r0 * 136 + nd * 8 + 2 * t4);
                float2 rb = *reinterpret_cast<const float2*>(red + (r0 + 8) * 136 + nd * 8 + 2 * t4);
                *reinterpret_cast<float2*>(ob + r0 * Ddim + nd * 8 + 2 * t4) =
                    make_float2(O[mb][nd][0] + ra.x, O[mb][nd][1] + ra.y);
                *reinterpret_cast<float2*>(ob + (r0 + 8) * Ddim + nd * 8 + 2 * t4) =
                    make_float2(O[mb][nd][2] + rb.x, O[mb][nd][3] + rb.y);
            }
        }
    }
}

extern "C" void kernel_launch(void* const* d_in, const int* in_sizes, int n_in,
                              void* d_out, int out_size) {
    (void)in_sizes; (void)n_in; (void)out_size;
    const float* q = (const float*)d_in[0];
    const float* k = (const float*)d_in[1];
    const float* v = (const float*)d_in[2];
    const float* scale = (const float*)d_in[3];
    float* out = (float*)d_out;

    cudaFuncSetAttribute(attn_relu2_kernel,
                         cudaFuncAttributeMaxDynamicSharedMemorySize, SMEM_BYTES);

    dim3 grid(Bdim * Hdim * (Sdim / 128));   // 512 CTAs
    attn_relu2_kernel<<<grid, NTHREADS, SMEM_BYTES>>>(q, k, v, scale, out);
}

// round 4
// speedup vs baseline: 1.0726x; 1.0726x over previous
#include <cuda_runtime.h>
#include <cstdint>

#define Bdim 2
#define Hdim 16
#define Sdim 2048
#define Ddim 128
#define QT 64            // q-tile rows per CTA
#define KT 64            // kv-tile rows
#define NT (Sdim / KT)   // 32 kv tiles
#define NTHREADS 256

// smem strides (floats): bank-conflict-free fragment access (verified mod-32)
#define QSTRIDE 136
#define KSTRIDE 136
#define VSTRIDE 132

#define QS_OFF 0
#define KS_OFF (QT * QSTRIDE)
#define VS_OFF (KS_OFF + KT * KSTRIDE)
#define SMEM_WORDS (VS_OFF + KT * VSTRIDE)
#define SMEM_BYTES (SMEM_WORDS * 4)    // 103424 -> 2 CTAs/SM

#define SHIFT1 1.00048828125f   // 1 + 2^-11 : Q-side truncation-bias compensation
#define SHIFTH 1.00024411f      // sqrt(1 + 2^-11) : P-side (applied before square)

// ---------------------------------------------------------------------------
static __device__ __forceinline__ uint32_t cvt_tf32(float f) {
    uint32_t r;
    asm("cvt.rna.tf32.f32 %0, %1;" : "=r"(r) : "f"(f));
    return r;
}

static __device__ __forceinline__ void mma8(float* d,
        uint32_t a0, uint32_t a1, uint32_t a2, uint32_t a3,
        uint32_t b0, uint32_t b1) {
    asm volatile(
        "mma.sync.aligned.m16n8k8.row.col.f32.tf32.tf32.f32 "
        "{%0,%1,%2,%3}, {%4,%5,%6,%7}, {%8,%9}, {%0,%1,%2,%3};"
        : "+f"(d[0]), "+f"(d[1]), "+f"(d[2]), "+f"(d[3])
        : "r"(a0), "r"(a1), "r"(a2), "r"(a3), "r"(b0), "r"(b1));
}

static __device__ __forceinline__ void cp16(const float* smem_dst, const float* gsrc) {
    unsigned sa = (unsigned)__cvta_generic_to_shared(smem_dst);
    asm volatile("cp.async.cg.shared.global [%0], [%1], 16;" :: "r"(sa), "l"(gsrc));
}
#define CP_COMMIT() asm volatile("cp.async.commit_group;" ::: "memory")
#define CP_WAIT(n)  asm volatile("cp.async.wait_group %0;" :: "n"(n) : "memory")

static __device__ __forceinline__ void bar_sync(int id, int cnt) {
    asm volatile("bar.sync %0, %1;" :: "r"(id), "r"(cnt) : "memory");
}

// Issue cp.async for one kv-quarter (16 rows of K and V) of tile `tile`.
// Called by 128 threads of the kv-group that owns quarter qq; tid_h in [0,128).
static __device__ __forceinline__ void issue_quarter(
        float* sm, const float* __restrict__ kb, const float* __restrict__ vb,
        int qq, int tile, int tid_h) {
    const float* kg = kb + (size_t)(tile * KT + qq * 16) * Ddim;
    const float* vg = vb + (size_t)(tile * KT + qq * 16) * Ddim;
    #pragma unroll
    for (int i = 0; i < 4; i++) {
        int c = tid_h + 128 * i;          // 0..511
        int r = c >> 5, col = (c & 31) << 2;
        cp16(sm + KS_OFF + (qq * 16 + r) * KSTRIDE + col, kg + r * Ddim + col);
    }
    #pragma unroll
    for (int i = 0; i < 4; i++) {
        int c = tid_h + 128 * i;
        int r = c >> 5, col = (c & 31) << 2;
        cp16(sm + VS_OFF + (qq * 16 + r) * VSTRIDE + col, vg + r * Ddim + col);
    }
}

// ---------------------------------------------------------------------------
// One CTA = one (b,h) x one 64-row q-tile. 8 warps: wm = wid&3 (m16 block),
// wn = wid>>2 (kv-half of 32 rows within the 64-row kv tile). Two CTAs/SM.
// Per phase (kv-quarter 16): S(m16 x kv16) -> P in regs (C->A reuse) ->
// O(m16 x d128) += P @ V. kv-halves decoupled on named barriers with
// quarter-granular cp.async pipelines. O reduced across halves at the end.
// ---------------------------------------------------------------------------
__global__ void __launch_bounds__(NTHREADS, 2)
attn_relu2_kernel(const float* __restrict__ q, const float* __restrict__ k,
                  const float* __restrict__ v, const float* __restrict__ scale_p,
                  float* __restrict__ out) {
    extern __shared__ float sm[];
    float* QS = sm + QS_OFF;
    float* KS = sm + KS_OFF;
    float* VS = sm + VS_OFF;

    const int tid  = threadIdx.x;
    const int lane = tid & 31;
    const int g    = lane >> 2;    // 0..7
    const int t4   = lane & 3;     // 0..3
    const int wid  = tid >> 5;
    const int wm   = wid & 3;      // m16 block
    const int wn   = wid >> 2;     // kv-half group
    const int tid_h = tid & 127;

    const int bh = blockIdx.x >> 5;           // 0..31
    const int q0 = (blockIdx.x & 31) << 6;    // q-tile base (64 rows)

    const float* kbase = k + (size_t)bh * Sdim * Ddim;
    const float* vbase = v + (size_t)bh * Sdim * Ddim;

    // ---- prologue: stream tile-0 quarters, fill Q ----
    issue_quarter(sm, kbase, vbase, wn * 2 + 0, 0, tid_h); CP_COMMIT();
    issue_quarter(sm, kbase, vbase, wn * 2 + 1, 0, tid_h); CP_COMMIT();

    {
        const float scl2 = (*scale_p) * SHIFT1;
        const float* qg = q + ((size_t)bh * Sdim + q0) * Ddim;
        #pragma unroll
        for (int i = 0; i < 8; i++) {
            int c = tid + 256 * i;         // 0..2047
            int r = c >> 5, col = (c & 31) << 2;
            float4 f = *reinterpret_cast<const float4*>(qg + r * Ddim + col);
            uint4 u;
            u.x = cvt_tf32(f.x * scl2); u.y = cvt_tf32(f.y * scl2);
            u.z = cvt_tf32(f.z * scl2); u.w = cvt_tf32(f.w * scl2);
            *reinterpret_cast<uint4*>(QS + r * QSTRIDE + col) = u;
        }
    }
    __syncthreads();

    float O[16][4];
    #pragma unroll
    for (int nd = 0; nd < 16; nd++)
        #pragma unroll
        for (int i = 0; i < 4; i++) O[nd][i] = 0.0f;

    // ---- main loop ----
    #pragma unroll 1
    for (int tt = 0; tt < NT; tt++) {
        const bool lastt = (tt == NT - 1);
        #pragma unroll
        for (int p = 0; p < 2; p++) {
            const int qq = wn * 2 + p;     // kv-quarter owned this phase

            if (lastt && p == 1) { CP_WAIT(0); } else { CP_WAIT(1); }
            bar_sync(1 + wn, 128);

            // ---- GEMM1: S = Qs @ K^T over d (16 k-steps) ----
            float S[2][4];
            #pragma unroll
            for (int nb = 0; nb < 2; nb++)
                #pragma unroll
                for (int i = 0; i < 4; i++) S[nb][i] = 0.0f;

            const float* qrow0 = QS + (wm * 16 + g) * QSTRIDE + 2 * t4;
            const float* krow0 = KS + (qq * 16 + g) * KSTRIDE + 2 * t4;
            #pragma unroll 4
            for (int ks = 0; ks < 16; ks++) {
                uint2 A0 = *reinterpret_cast<const uint2*>(qrow0 + 8 * ks);
                uint2 A1 = *reinterpret_cast<const uint2*>(qrow0 + 8 * QSTRIDE + 8 * ks);
                #pragma unroll
                for (int nb = 0; nb < 2; nb++) {
                    float2 b = *reinterpret_cast<const float2*>(
                        krow0 + nb * 8 * KSTRIDE + 8 * ks);
                    mma8(S[nb], A0.x, A1.x, A0.y, A1.y,
                         __float_as_uint(b.x), __float_as_uint(b.y));
                }
            }

            // ---- P = tf32(relu(S)^2 * shift); GEMM2: O += P @ V ----
            #pragma unroll
            for (int s2 = 0; s2 < 2; s2++) {
                uint32_t pA[4];
                #pragma unroll
                for (int i = 0; i < 4; i++) {
                    float f = fmaxf(S[s2][i], 0.0f) * SHIFTH;
                    pA[i] = cvt_tf32(f * f);
                }
                const float* vrow = VS + (qq * 16 + s2 * 8 + 2 * t4) * VSTRIDE + g;
                #pragma unroll 8
                for (int nd = 0; nd < 16; nd++) {
                    uint32_t b0 = __float_as_uint(vrow[nd * 8]);
                    uint32_t b1 = __float_as_uint(vrow[nd * 8 + VSTRIDE]);
                    // A-frag = (c0, c2, c1, c3) of the S block (k-order permute)
                    mma8(O[nd], pA[0], pA[2], pA[1], pA[3], b0, b1);
                }
            }

            bar_sync(1 + wn, 128);
            if (!lastt) {
                issue_quarter(sm, kbase, vbase, qq, tt + 1, tid_h);
                CP_COMMIT();
            }
        }
    }

    // ---- reduce O across the two kv-halves, write out ----
    __syncthreads();
    float* red = KS;   // reuse 64 x 136 region
    if (wn == 1) {
        int r0 = wm * 16 + g;
        #pragma unroll
        for (int nd = 0; nd < 16; nd++) {
            *reinterpret_cast<float2*>(red + r0 * 136 + nd * 8 + 2 * t4) =
                make_float2(O[nd][0], O[nd][1]);
            *reinterpret_cast<float2*>(red + (r0 + 8) * 136 + nd * 8 + 2 * t4) =
                make_float2(O[nd][2], O[nd][3]);
        }
    }
    __syncthreads();
    if (wn == 0) {
        float* ob = out + ((size_t)bh * Sdim + q0) * Ddim;
        int r0 = wm * 16 + g;
        #pragma unroll
        for (int nd = 0; nd < 16; nd++) {
            float2 ra = *reinterpret_cast<const float2*>(red + r0 * 136 + nd * 8 + 2 * t4);
            float2 rb = *reinterpret_cast<const float2*>(red + (r0 + 8) * 136 + nd * 8 + 2 * t4);
            *reinterpret_cast<float2*>(ob + r0 * Ddim + nd * 8 + 2 * t4) =
                make_float2(O[nd][0] + ra.x, O[nd][1] + ra.y);
            *reinterpret_cast<float2*>(ob + (r0 + 8) * Ddim + nd * 8 + 2 * t4) =
                make_float2(O[nd][2] + rb.x, O[nd][3] + rb.y);
        }
    }
}

extern "C" void kernel_launch(void* const* d_in, const int* in_sizes, int n_in,
                              void* d_out, int out_size) {
    (void)in_sizes; (void)n_in; (void)out_size;
    const float* q = (const float*)d_in[0];
    const float* k = (const float*)d_in[1];
    const float* v = (const float*)d_in[2];
    const float* scale = (const float*)d_in[3];
    float* out = (float*)d_out;

    cudaFuncSetAttribute(attn_relu2_kernel,
                         cudaFuncAttributeMaxDynamicSharedMemorySize, SMEM_BYTES);

    dim3 grid(Bdim * Hdim * (Sdim / QT));   // 1024 CTAs, bh-major
    attn_relu2_kernel<<<grid, NTHREADS, SMEM_BYTES>>>(q, k, v, scale, out);
}